// round 17
// baseline (speedup 1.0000x reference)
#include <cuda_runtime.h>
#include <math_constants.h>
#include <stdint.h>

// PQHead: out[b, m*6+d] = codebooks[m, argmax_k <x[b,m*6:...], cb[m,k,:]>, d]
// (forward value of the straight-through estimator == discrete codeword)
//
// FROZEN NUMERICS: dot = x0*c0 then fma.rn chain d=1..5 (scalar FFMA), argmax
// exact, FIRST-max tie rule. ~2 argmax flips total breach 1e-3.
//
// LESSONS: R3/R4 spills; R7 f32x2 half-rate; R12 cp.async; R13 LDS slot law
// (cb cost = 6/RPT_rows wf/pair, layout-invariant); R14/R16 prefetch.L1 and
// discarded-LDG touches useless/harmful -> ONLY full register prefetch works.
// R9 (RPT=2+prefetch): crossbar 70% loaded -> LDS queueing caps issue at 69%.
// R17: RPT=3 + full register prefetch fits 64 regs; crossbar load drops to
// ~52%. Partial last tile handled with clamped loads + predicated stores.

#define B_ROWS   32768
#define M_SUB    128
#define QM       16                      // m's per block (1/8 split)
#define NGRP     (M_SUB / QM)            // 8
#define K_CODES  32
#define D_SUB    6
#define DIM      768
#define RPT      3                       // rows per thread
#define TPB      256                     // 16 row-groups x 16 m
#define TILE_ROWS (RPT * (TPB / QM))     // 48
#define NTILES   ((B_ROWS + TILE_ROWS - 1) / TILE_ROWS)   // 683 (last partial)
#define BLK_PER_G 74                     // 8 groups x 74 = 592 = 4/SM
#define NBLOCKS  (NGRP * BLK_PER_G)

__global__ void __launch_bounds__(TPB, 4)
pq_head_kernel(const float* __restrict__ x,
               const float* __restrict__ cb,
               float* __restrict__ out)
{
    // Codebook split: cbA[k*16+m] = (d0,d1,d2,d3), cbB[k*16+m] = (d4,d5).
    __shared__ float4 cbA[K_CODES * QM];     // 8KB
    __shared__ float2 cbB[K_CODES * QM];     // 4KB

    const int t = threadIdx.x;
    const int grp = blockIdx.x / BLK_PER_G;      // which m-group this block owns
    const int bstart = blockIdx.x % BLK_PER_G;

    // One-time codebook load for this group.
    {
        const float* cbg = cb + (size_t)grp * QM * (K_CODES * D_SUB);
        for (int i = t; i < QM * K_CODES; i += TPB) {
            int mloc = i / K_CODES;
            int k    = i - mloc * K_CODES;
            const float* src = cbg + (size_t)mloc * (K_CODES * D_SUB) + k * D_SUB;
            cbA[k * QM + mloc] = make_float4(src[0], src[1], src[2], src[3]);
            cbB[k * QM + mloc] = make_float2(src[4], src[5]);
        }
    }
    __syncthreads();

    const int mloc = t & (QM - 1);
    const int g    = t >> 4;             // row-group 0..15
    const int col0 = (grp * QM + mloc) * D_SUB;

    // Prologue: load first tile's rows (clamped -- only last tile is partial).
    float xv[RPT][D_SUB];
    {
        const int b0 = bstart * TILE_ROWS + g * RPT;
        #pragma unroll
        for (int r = 0; r < RPT; r++) {
            int br = min(b0 + r, B_ROWS - 1);
            const float2* p = reinterpret_cast<const float2*>(
                x + (size_t)br * DIM + col0);
            float2 a = p[0], bq = p[1], c = p[2];
            xv[r][0] = a.x;  xv[r][1] = a.y;
            xv[r][2] = bq.x; xv[r][3] = bq.y;
            xv[r][4] = c.x;  xv[r][5] = c.y;
        }
    }

    for (int tile = bstart; tile < NTILES; tile += BLK_PER_G) {
        const int b0 = tile * TILE_ROWS + g * RPT;

        // ---- Register prefetch of next tile's rows (always clamped; values
        // are discarded if the loop ends, clamping makes addresses safe).
        const int b0n = b0 + BLK_PER_G * TILE_ROWS;
        float nx[RPT][D_SUB];
        #pragma unroll
        for (int r = 0; r < RPT; r++) {
            int br = min(b0n + r, B_ROWS - 1);
            const float2* p = reinterpret_cast<const float2*>(
                x + (size_t)br * DIM + col0);
            float2 a = p[0], bq = p[1], c = p[2];
            nx[r][0] = a.x;  nx[r][1] = a.y;
            nx[r][2] = bq.x; nx[r][3] = bq.y;
            nx[r][4] = c.x;  nx[r][5] = c.y;
        }

        // ---- k = 0 peeled: best = dot, idx = 0.
        float best[RPT];
        int   idx[RPT];
        {
            const float4 ca  = cbA[mloc];
            const float2 cbv = cbB[mloc];
            #pragma unroll
            for (int r = 0; r < RPT; r++) {
                float dot = xv[r][0] * ca.x;
                dot = fmaf(xv[r][1], ca.y, dot);
                dot = fmaf(xv[r][2], ca.z, dot);
                dot = fmaf(xv[r][3], ca.w, dot);
                dot = fmaf(xv[r][4], cbv.x, dot);
                dot = fmaf(xv[r][5], cbv.y, dot);
                best[r] = dot;
                idx[r]  = 0;
            }
        }

        // ---- k = 1..31; bounded unroll keeps the live set under 64 regs.
        #pragma unroll 2
        for (int k = 1; k < K_CODES; k++) {
            const float4 ca  = cbA[k * QM + mloc];
            const float2 cbv = cbB[k * QM + mloc];
            #pragma unroll
            for (int r = 0; r < RPT; r++) {
                float dot = xv[r][0] * ca.x;
                dot = fmaf(xv[r][1], ca.y, dot);
                dot = fmaf(xv[r][2], ca.z, dot);
                dot = fmaf(xv[r][3], ca.w, dot);
                dot = fmaf(xv[r][4], cbv.x, dot);
                dot = fmaf(xv[r][5], cbv.y, dot);
                // EXACT argmax, FIRST-max tie rule; FMNMX value chain keeps
                // the 13-cyc predicate latency off the loop-carried path.
                bool p  = dot > best[r];
                best[r] = fmaxf(best[r], dot);
                idx[r]  = p ? k : idx[r];
            }
        }

        // ---- Emit the winning codeword rows (predicated on valid row).
        #pragma unroll
        for (int r = 0; r < RPT; r++) {
            if (b0 + r < B_ROWS) {
                const float4 oa = cbA[idx[r] * QM + mloc];
                const float2 ob = cbB[idx[r] * QM + mloc];
                float2* po = reinterpret_cast<float2*>(
                    out + (size_t)(b0 + r) * DIM + col0);
                po[0] = make_float2(oa.x, oa.y);
                po[1] = make_float2(oa.z, oa.w);
                po[2] = ob;
            }
        }

        // ---- Rotate prefetched registers in.
        #pragma unroll
        for (int r = 0; r < RPT; r++)
            #pragma unroll
            for (int d = 0; d < D_SUB; d++)
                xv[r][d] = nx[r][d];
    }
}

extern "C" void kernel_launch(void* const* d_in, const int* in_sizes, int n_in,
                              void* d_out, int out_size)
{
    const float* x  = (const float*)d_in[0];
    const float* cb = (const float*)d_in[1];
    float* out      = (float*)d_out;

    pq_head_kernel<<<NBLOCKS, TPB>>>(x, cb, out);
}